// round 1
// baseline (speedup 1.0000x reference)
#include <cuda_runtime.h>
#include <cuda_fp16.h>
#include <cstdint>

// Problem constants
#define NSEQ  16384      // B*Ns = 32*512
#define TLEN  128
#define CDIM  25
#define PDIM  20
#define HDIM  25
#define NPAIR 40         // padded gate slots: 3 gates x 26 units + 2 pad = 80 -> 40 pairs
// pair p: gate g = p/13 (g==3 -> pad pair 39), q = p%13, units u0=2q, u1=2q+1 (u<25 valid)

typedef unsigned long long ull;

// ---------------- packed f32x2 helpers (sm_100+ only, ptxas never auto-emits) -------------
__device__ __forceinline__ ull ffma2(ull a, ull b, ull c) {
    ull d;
    asm("fma.rn.f32x2 %0, %1, %2, %3;" : "=l"(d) : "l"(a), "l"(b), "l"(c));
    return d;
}
__device__ __forceinline__ ull fdup(float v) {
    ull r;
    asm("mov.b64 %0, {%1, %1};" : "=l"(r) : "f"(v));
    return r;
}
__device__ __forceinline__ void f2unpack(ull v, float& lo, float& hi) {
    asm("mov.b64 {%0, %1}, %2;" : "=f"(lo), "=f"(hi) : "l"(v));
}
__device__ __forceinline__ float ex2f(float x) {
    float r; asm("ex2.approx.f32 %0, %1;" : "=f"(r) : "f"(x)); return r;
}
__device__ __forceinline__ float rcpf(float x) {
    float r; asm("rcp.approx.f32 %0, %1;" : "=f"(r) : "f"(x)); return r;
}
// sigmoid(x) = 1/(1+2^(-x*log2e));  tanh(x) = 2/(1+2^(-2x*log2e)) - 1   (~1e-6 accurate)
__device__ __forceinline__ float sigf(float x) {
    return rcpf(1.0f + ex2f(-1.4426950408889634f * x));
}
__device__ __forceinline__ float tanhfast(float x) {
    float e = ex2f(-2.8853900817779268f * x);
    return fmaf(2.0f, rcpf(1.0f + e), -1.0f);
}
__device__ __forceinline__ ull pkbits(float lo, float hi) {
    return (ull)__float_as_uint(lo) | ((ull)__float_as_uint(hi) << 32);
}

// ---------------- device scratch (static: no allocation) ----------------
__device__ ull g_pW1[CDIM * 10];        // [k][jp] pairs of W1 columns
__device__ ull g_pb1[10];
__device__ ull g_pWih[PDIM * NPAIR];    // [k][pair] padded-slot layout
__device__ ull g_bias_gx[NPAIR];        // b_ih (+ b_hh for r,z gates) in padded slots
__device__ ull g_pWhh[HDIM * NPAIR];    // [k][pair] padded-slot layout
__device__ ull g_acc_init[NPAIR];       // b_hh for n gate only (stays recurrent-side)
__device__ __half2 g_gx[(size_t)TLEN * NSEQ * NPAIR];  // 335 MB scratch, [t][n][pair]

// ---------------- prep: pack weights ----------------
__global__ void prep_kernel(const float* __restrict__ W1, const float* __restrict__ b1,
                            const float* __restrict__ Wih, const float* __restrict__ Whh,
                            const float* __restrict__ bih, const float* __restrict__ bhh) {
    int tid = threadIdx.x;
    for (int i = tid; i < CDIM * 10; i += blockDim.x) {
        int k = i / 10, jp = i % 10;
        g_pW1[i] = pkbits(W1[(2 * jp) * CDIM + k], W1[(2 * jp + 1) * CDIM + k]);
    }
    for (int i = tid; i < 10; i += blockDim.x)
        g_pb1[i] = pkbits(b1[2 * i], b1[2 * i + 1]);

    for (int i = tid; i < PDIM * NPAIR; i += blockDim.x) {
        int k = i / NPAIR, p = i % NPAIR;
        int g = p / 13, q = p % 13;
        float lo = 0.f, hi = 0.f;
        if (g < 3) {
            int u0 = 2 * q, u1 = u0 + 1;
            if (u0 < 25) lo = Wih[(g * 25 + u0) * PDIM + k];
            if (u1 < 25) hi = Wih[(g * 25 + u1) * PDIM + k];
        }
        g_pWih[i] = pkbits(lo, hi);
    }
    for (int i = tid; i < HDIM * NPAIR; i += blockDim.x) {
        int k = i / NPAIR, p = i % NPAIR;
        int g = p / 13, q = p % 13;
        float lo = 0.f, hi = 0.f;
        if (g < 3) {
            int u0 = 2 * q, u1 = u0 + 1;
            if (u0 < 25) lo = Whh[(g * 25 + u0) * HDIM + k];
            if (u1 < 25) hi = Whh[(g * 25 + u1) * HDIM + k];
        }
        g_pWhh[i] = pkbits(lo, hi);
    }
    for (int i = tid; i < NPAIR; i += blockDim.x) {
        int p = i, g = p / 13, q = p % 13;
        float lo = 0.f, hi = 0.f;
        if (g < 3) {
            int u0 = 2 * q, u1 = u0 + 1;
            if (u0 < 25) lo = bih[g * 25 + u0] + (g < 2 ? bhh[g * 25 + u0] : 0.f);
            if (u1 < 25) hi = bih[g * 25 + u1] + (g < 2 ? bhh[g * 25 + u1] : 0.f);
        }
        g_bias_gx[i] = pkbits(lo, hi);
    }
    for (int i = tid; i < NPAIR; i += blockDim.x) {
        int p = i, g = p / 13, q = p % 13;
        float lo = 0.f, hi = 0.f;
        if (g == 2) {
            int u0 = 2 * q, u1 = u0 + 1;
            if (u0 < 25) lo = bhh[50 + u0];
            if (u1 < 25) hi = bhh[50 + u1];
        }
        g_acc_init[i] = pkbits(lo, hi);
    }
}

// ---------------- K1: gx = leakyrelu(x@W1^T + b1) @ Wih^T + biases  -> fp16 -----------
// 2 rows (t, t+1) per thread; lanes = consecutive n for coalesced stores.
__global__ __launch_bounds__(128, 1) void gx_kernel(const float* __restrict__ x) {
    __shared__ ull sW1[CDIM * 10];
    __shared__ ull sb1[10];
    __shared__ ull sWih[PDIM * NPAIR];
    __shared__ ull sbias[NPAIR];
    for (int i = threadIdx.x; i < CDIM * 10; i += 128) sW1[i] = g_pW1[i];
    for (int i = threadIdx.x; i < 10; i += 128) sb1[i] = g_pb1[i];
    for (int i = threadIdx.x; i < PDIM * NPAIR; i += 128) sWih[i] = g_pWih[i];
    for (int i = threadIdx.x; i < NPAIR; i += 128) sbias[i] = g_bias_gx[i];
    __syncthreads();

    int n = blockIdx.x * 128 + threadIdx.x;
    int t0 = blockIdx.y * 2;

    // load x rows t0, t0+1 : 50 contiguous floats (8B-aligned since t0 even)
    const float2* xp = reinterpret_cast<const float2*>(x + ((size_t)n * TLEN + t0) * CDIM);
    float xv[50];
#pragma unroll
    for (int i = 0; i < 25; i++) {
        float2 v = __ldg(xp + i);
        xv[2 * i] = v.x; xv[2 * i + 1] = v.y;
    }

    // projection: p = x@W1^T + b1 (packed across output pairs, weight reuse across rows)
    ull pa0[10], pa1[10];
#pragma unroll
    for (int j = 0; j < 10; j++) { pa0[j] = sb1[j]; pa1[j] = sb1[j]; }
#pragma unroll
    for (int k = 0; k < CDIM; k++) {
        ull d0 = fdup(xv[k]);
        ull d1 = fdup(xv[25 + k]);
        const ulonglong2* row = reinterpret_cast<const ulonglong2*>(&sW1[k * 10]);
#pragma unroll
        for (int j = 0; j < 5; j++) {
            ulonglong2 w = row[j];
            pa0[2 * j]     = ffma2(w.x, d0, pa0[2 * j]);
            pa0[2 * j + 1] = ffma2(w.y, d0, pa0[2 * j + 1]);
            pa1[2 * j]     = ffma2(w.x, d1, pa1[2 * j]);
            pa1[2 * j + 1] = ffma2(w.y, d1, pa1[2 * j + 1]);
        }
    }
    // LeakyReLU(v) = max(v, 0.01v)
    float pv0[20], pv1[20];
#pragma unroll
    for (int j = 0; j < 10; j++) {
        float a, b;
        f2unpack(pa0[j], a, b);
        pv0[2 * j] = fmaxf(a, 0.01f * a); pv0[2 * j + 1] = fmaxf(b, 0.01f * b);
        f2unpack(pa1[j], a, b);
        pv1[2 * j] = fmaxf(a, 0.01f * a); pv1[2 * j + 1] = fmaxf(b, 0.01f * b);
    }

    uint4* dst0 = reinterpret_cast<uint4*>(g_gx + ((size_t)t0 * NSEQ + n) * NPAIR);
    uint4* dst1 = reinterpret_cast<uint4*>(g_gx + ((size_t)(t0 + 1) * NSEQ + n) * NPAIR);

    // gx stage in 2 chunks of 20 pairs to bound register pressure
#pragma unroll
    for (int c = 0; c < 2; c++) {
        ull ga0[20], ga1[20];
#pragma unroll
        for (int q = 0; q < 20; q++) { ga0[q] = sbias[c * 20 + q]; ga1[q] = sbias[c * 20 + q]; }
#pragma unroll
        for (int k = 0; k < PDIM; k++) {
            ull d0 = fdup(pv0[k]);
            ull d1 = fdup(pv1[k]);
            const ulonglong2* row =
                reinterpret_cast<const ulonglong2*>(&sWih[k * NPAIR + c * 20]);
#pragma unroll
            for (int q = 0; q < 10; q++) {
                ulonglong2 w = row[q];
                ga0[2 * q]     = ffma2(w.x, d0, ga0[2 * q]);
                ga0[2 * q + 1] = ffma2(w.y, d0, ga0[2 * q + 1]);
                ga1[2 * q]     = ffma2(w.x, d1, ga1[2 * q]);
                ga1[2 * q + 1] = ffma2(w.y, d1, ga1[2 * q + 1]);
            }
        }
        union { __half2 h2[20]; uint4 v4[5]; } ob0, ob1;
#pragma unroll
        for (int q = 0; q < 20; q++) {
            float a, b;
            f2unpack(ga0[q], a, b);
            ob0.h2[q] = __floats2half2_rn(a, b);
            f2unpack(ga1[q], a, b);
            ob1.h2[q] = __floats2half2_rn(a, b);
        }
#pragma unroll
        for (int i = 0; i < 5; i++) {
            dst0[c * 5 + i] = ob0.v4[i];
            dst1[c * 5 + i] = ob1.v4[i];
        }
    }
}

// ---------------- K2: GRU scan, thread-per-sequence ----------------
__global__ __launch_bounds__(128, 1) void gru_kernel(float* __restrict__ out) {
    __shared__ ull sW[HDIM * NPAIR];   // 8 KB, broadcast reads
    __shared__ ull sInit[NPAIR];
    for (int i = threadIdx.x; i < HDIM * NPAIR; i += 128) sW[i] = g_pWhh[i];
    for (int i = threadIdx.x; i < NPAIR; i += 128) sInit[i] = g_acc_init[i];
    __syncthreads();

    int n = blockIdx.x * 128 + threadIdx.x;
    float h[26];
#pragma unroll
    for (int u = 0; u < 26; u++) h[u] = 0.f;

#pragma unroll 1
    for (int t = 0; t < TLEN; t++) {
        // issue gx loads first; latency hidden under the 25x40 FFMA2 dot loop
        union { uint4 v4[10]; __half2 h2[40]; } gx;
        const uint4* gp = reinterpret_cast<const uint4*>(g_gx + ((size_t)t * NSEQ + n) * NPAIR);
#pragma unroll
        for (int i = 0; i < 10; i++) gx.v4[i] = __ldg(gp + i);

        ull acc[NPAIR];
#pragma unroll
        for (int p = 0; p < NPAIR; p++) acc[p] = sInit[p];
#pragma unroll
        for (int k = 0; k < HDIM; k++) {
            ull hd = fdup(h[k]);
            const ulonglong2* row = reinterpret_cast<const ulonglong2*>(&sW[k * NPAIR]);
#pragma unroll
            for (int p = 0; p < 20; p++) {
                ulonglong2 w = row[p];
                acc[2 * p]     = ffma2(w.x, hd, acc[2 * p]);
                acc[2 * p + 1] = ffma2(w.y, hd, acc[2 * p + 1]);
            }
        }
        // gates (pairs never straddle gate boundaries: r = pairs 0-12, z = 13-25, n = 26-38)
#pragma unroll
        for (int p = 0; p < 13; p++) {
            float2 gr = __half22float2(gx.h2[p]);
            float2 gz = __half22float2(gx.h2[13 + p]);
            float2 gn = __half22float2(gx.h2[26 + p]);
            float arl, arh; f2unpack(acc[p], arl, arh);
            float azl, azh; f2unpack(acc[13 + p], azl, azh);
            float anl, anh; f2unpack(acc[26 + p], anl, anh);
            float rl = sigf(gr.x + arl), rh = sigf(gr.y + arh);
            float zl = sigf(gz.x + azl), zh = sigf(gz.y + azh);
            float nl = tanhfast(fmaf(rl, anl, gn.x));
            float nh = tanhfast(fmaf(rh, anh, gn.y));
            h[2 * p]     = fmaf(zl, h[2 * p] - nl, nl);
            h[2 * p + 1] = fmaf(zh, h[2 * p + 1] - nh, nh);
        }
    }
#pragma unroll
    for (int u = 0; u < HDIM; u++) out[(size_t)n * HDIM + u] = h[u];
}

// ---------------- launcher ----------------
extern "C" void kernel_launch(void* const* d_in, const int* in_sizes, int n_in,
                              void* d_out, int out_size) {
    (void)in_sizes; (void)n_in; (void)out_size;
    const float* x   = (const float*)d_in[0];
    const float* W1  = (const float*)d_in[1];
    const float* b1  = (const float*)d_in[2];
    const float* Wih = (const float*)d_in[3];
    const float* Whh = (const float*)d_in[4];
    const float* bih = (const float*)d_in[5];
    const float* bhh = (const float*)d_in[6];

    prep_kernel<<<1, 256>>>(W1, b1, Wih, Whh, bih, bhh);
    gx_kernel<<<dim3(NSEQ / 128, TLEN / 2), 128>>>(x);
    gru_kernel<<<NSEQ / 128, 128>>>((float*)d_out);
}